// round 13
// baseline (speedup 1.0000x reference)
#include <cuda_runtime.h>
#include <cuda_bf16.h>
#include <cfloat>
#include <math.h>
#include <stdint.h>

#define BS_N    4096
#define HID     2048
#define KDIM    256
#define KEY_NUM 512
#define HEAD    2
#define RANK    2
#define KNN     16
#define VDIM    512

// G = KDIM^-0.4 = 256^-0.4 = 2^-3.2
#define GW      0.10881882041201557f

// ---------------- scratch (device globals; no runtime allocation) ----------------
__device__ __align__(256) float g_q   [4][BS_N * 2 * KDIM]; // split-K partials
__device__ __align__(256) float g_qln [BS_N * 2 * KDIM];
__device__ __align__(256) float g_knw [HEAD * 2 * KEY_NUM * RANK * KDIM];
__device__ __align__(256) float g_a   [2][BS_N * HEAD * KEY_NUM];
__device__ int   g_vidx[BS_N * HEAD * KNN];
__device__ float g_w   [BS_N * HEAD * KNN];

// bf16 hi/lo split operands for tensor-core GEMMs
__device__ __align__(256) __nv_bfloat16 g_xhi [BS_N * HID];
__device__ __align__(256) __nv_bfloat16 g_xlo [BS_N * HID];
__device__ __align__(256) __nv_bfloat16 g_wqhi[2 * KDIM * HID];
__device__ __align__(256) __nv_bfloat16 g_wqlo[2 * KDIM * HID];
__device__ __align__(256) __nv_bfloat16 g_qlnhi[BS_N * 2 * KDIM];
__device__ __align__(256) __nv_bfloat16 g_qlnlo[BS_N * 2 * KDIM];
__device__ __align__(256) __nv_bfloat16 g_knuhi[2 * HEAD * KEY_NUM * KDIM];
__device__ __align__(256) __nv_bfloat16 g_knulo[2 * HEAD * KEY_NUM * KDIM];
__device__ __align__(256) __nv_bfloat16 g_ovhi[BS_N * VDIM];
__device__ __align__(256) __nv_bfloat16 g_ovlo[BS_N * VDIM];
__device__ __align__(256) __nv_bfloat16 g_vphi[HID * VDIM];
__device__ __align__(256) __nv_bfloat16 g_vplo[HID * VDIM];

// ================================ PTX helpers =====================================
__device__ __forceinline__ uint32_t smem_u32(const void* p) {
    return (uint32_t)__cvta_generic_to_shared(p);
}
__device__ __forceinline__ void cp16(uint32_t s, const void* g) {
    asm volatile("cp.async.cg.shared.global [%0], [%1], 16;" :: "r"(s), "l"(g) : "memory");
}
__device__ __forceinline__ void ldsm_x4(uint32_t& r0, uint32_t& r1, uint32_t& r2, uint32_t& r3,
                                        uint32_t addr) {
    asm volatile("ldmatrix.sync.aligned.m8n8.x4.shared.b16 {%0,%1,%2,%3}, [%4];"
                 : "=r"(r0), "=r"(r1), "=r"(r2), "=r"(r3) : "r"(addr));
}
__device__ __forceinline__ void mma16816(float* d, const uint32_t* a, uint32_t b0, uint32_t b1) {
    asm volatile(
        "mma.sync.aligned.m16n8k16.row.col.f32.bf16.bf16.f32 "
        "{%0,%1,%2,%3}, {%4,%5,%6,%7}, {%8,%9}, {%0,%1,%2,%3};"
        : "+f"(d[0]), "+f"(d[1]), "+f"(d[2]), "+f"(d[3])
        : "r"(a[0]), "r"(a[1]), "r"(a[2]), "r"(a[3]), "r"(b0), "r"(b1));
}

// SMEM tile geometry: rows x 32 bf16 = 64 B/row, XOR-swizzled 16B chunks.
// Bank-group position of (row,chunk) = (4*(row&1) + (chunk ^ ((row>>1)&3))) mod 8
// -> conflict-free for ldmatrix 8-row phases and cp.async 2-row x 4-chunk phases.
#define ROW_B 64
__device__ __forceinline__ uint32_t swz(int row, int chunk) {
    return (uint32_t)(row * ROW_B + ((chunk ^ ((row >> 1) & 3)) << 4));
}

// ============ bf16-split tensor-core GEMM:  C[M,N] = A[M,K] * B[N,K]^T (fp32) =====
// CTA tile 64 x 128, BK=32, 4 warps (2m x 2n, warp tile 32x64), 128 threads,
// cp.async 3-stage pipeline, XOR-swizzled smem, 3-term hi/lo split in fp32.
// A-frags reused across 64 n-cols: 24 ldsm feed 96 HMMAs per warp per chunk.
__global__ __launch_bounds__(128, 3) void mma_gemm(
    const __nv_bfloat16* __restrict__ Ahi, const __nv_bfloat16* __restrict__ Alo,
    const __nv_bfloat16* __restrict__ Bhi, const __nv_bfloat16* __restrict__ Blo,
    float* __restrict__ C, int lda, int ldb, int ldc, int nchunks,
    int a_koff_z, int b_koff_z, int b_noff_z, long long c_off_z)
{
    constexpr int BM     = 64;
    constexpr int WTN    = 64;             // warp tile n
    constexpr int FN     = 8;              // n8 frags
    constexpr int TILE_A = BM * ROW_B;     // 4096
    constexpr int TILE_B2 = 128 * ROW_B;   // 8192
    constexpr int STAGE  = 2 * TILE_A + 2 * TILE_B2;  // 24576

    extern __shared__ __align__(256) char smem[];
    const uint32_t sb = smem_u32(smem);
    const int t = threadIdx.x;
    const int wid = t >> 5, lane = t & 31;
    const int m0 = blockIdx.y * BM;
    const int nb = blockIdx.x * 128 + blockIdx.z * b_noff_z;  // B row base
    const int n0 = blockIdx.x * 128;                          // C col base
    const int aK0 = blockIdx.z * a_koff_z;
    const int bK0 = blockIdx.z * b_koff_z;
    C += (long long)blockIdx.z * c_off_z;

    const int wm = wid & 1;
    const int wn = wid >> 1;

    // ldmatrix lane geometry
    const int lm_row = (lane & 7) + ((lane >> 3) & 1) * 8;   // 0..15
    const int cbase = lane >> 4;                              // 0 or 1

    float acc[2][FN][4] = {};

    auto load_stage = [&](int i, int buf) {
        const uint32_t sbuf = sb + (uint32_t)buf * STAGE;
        const int kA = aK0 + i * 32;
        const int kB = bK0 + i * 32;
#pragma unroll
        for (int rep = 0; rep < 2; rep++) {
            const int idx = t + rep * 128;
            const int row = idx >> 2, c = idx & 3;
            const uint32_t so = swz(row, c);
            cp16(sbuf +          so, Ahi + (size_t)(m0 + row) * lda + kA + c * 8);
            cp16(sbuf + TILE_A + so, Alo + (size_t)(m0 + row) * lda + kA + c * 8);
        }
#pragma unroll
        for (int rep = 0; rep < 4; rep++) {
            const int idx = t + rep * 128;
            const int row = idx >> 2, c = idx & 3;
            const uint32_t so = swz(row, c);
            cp16(sbuf + 2 * TILE_A +           so, Bhi + (size_t)(nb + row) * ldb + kB + c * 8);
            cp16(sbuf + 2 * TILE_A + TILE_B2 + so, Blo + (size_t)(nb + row) * ldb + kB + c * 8);
        }
        asm volatile("cp.async.commit_group;" ::: "memory");
    };

    auto compute_stage = [&](int buf) {
        const uint32_t sbuf = sb + (uint32_t)buf * STAGE;
        const uint32_t sAhi = sbuf;
        const uint32_t sAlo = sbuf + TILE_A;
        const uint32_t sBhi = sbuf + 2 * TILE_A;
        const uint32_t sBlo = sbuf + 2 * TILE_A + TILE_B2;
#pragma unroll
        for (int kh = 0; kh < 2; kh++) {
            const int chunk = cbase + kh * 2;
            uint32_t ah[2][4], al[2][4];
#pragma unroll
            for (int fm = 0; fm < 2; fm++) {
                const int row = wm * 32 + fm * 16 + lm_row;
                const uint32_t ro = swz(row, chunk);
                ldsm_x4(ah[fm][0], ah[fm][1], ah[fm][2], ah[fm][3], sAhi + ro);
                ldsm_x4(al[fm][0], al[fm][1], al[fm][2], al[fm][3], sAlo + ro);
            }
#pragma unroll
            for (int f = 0; f < 4; f++) {            // each f covers n16
                const int row = wn * WTN + f * 16 + lm_row;
                const uint32_t ro = swz(row, chunk);
                uint32_t h0, h1, h2, h3, l0, l1, l2, l3;
                ldsm_x4(h0, h1, h2, h3, sBhi + ro);
                ldsm_x4(l0, l1, l2, l3, sBlo + ro);
                // term-major: 4 distinct accs per term; per-acc order hh->hl->lh
                mma16816(acc[0][f * 2],     ah[0], h0, h2);
                mma16816(acc[0][f * 2 + 1], ah[0], h1, h3);
                mma16816(acc[1][f * 2],     ah[1], h0, h2);
                mma16816(acc[1][f * 2 + 1], ah[1], h1, h3);
                mma16816(acc[0][f * 2],     ah[0], l0, l2);
                mma16816(acc[0][f * 2 + 1], ah[0], l1, l3);
                mma16816(acc[1][f * 2],     ah[1], l0, l2);
                mma16816(acc[1][f * 2 + 1], ah[1], l1, l3);
                mma16816(acc[0][f * 2],     al[0], h0, h2);
                mma16816(acc[0][f * 2 + 1], al[0], h1, h3);
                mma16816(acc[1][f * 2],     al[1], h0, h2);
                mma16816(acc[1][f * 2 + 1], al[1], h1, h3);
            }
        }
    };

    // 3-stage pipeline: two-ahead prefetch; iteration-top sync gates slot reuse.
    load_stage(0, 0);
    if (nchunks > 1) load_stage(1, 1);
    for (int i = 0; i < nchunks; i++) {
        if (i + 1 < nchunks) {
            asm volatile("cp.async.wait_group 1;" ::: "memory");
        } else {
            asm volatile("cp.async.wait_group 0;" ::: "memory");
        }
        __syncthreads();
        if (i + 2 < nchunks) load_stage(i + 2, (i + 2) % 3);
        compute_stage(i % 3);
    }

    // ---- epilogue: direct fp32 stores ----
    const int er = lane >> 2, ec = (lane & 3) * 2;
#pragma unroll
    for (int fm = 0; fm < 2; fm++) {
        const int row = m0 + wm * 32 + fm * 16 + er;
#pragma unroll
        for (int fn = 0; fn < FN; fn++) {
            const int col = n0 + wn * WTN + fn * 8 + ec;
            *(float2*)(C + (size_t)row * ldc + col) =
                make_float2(acc[fm][fn][0], acc[fm][fn][1]);
            *(float2*)(C + (size_t)(row + 8) * ldc + col) =
                make_float2(acc[fm][fn][2], acc[fm][fn][3]);
        }
    }
}

// ---------------- fp32 -> (bf16 hi, bf16 lo) elementwise split --------------------
__global__ void conv_kernel(const float* __restrict__ in,
                            __nv_bfloat16* __restrict__ hi, __nv_bfloat16* __restrict__ lo,
                            int n4)
{
    int i = blockIdx.x * blockDim.x + threadIdx.x;
    if (i >= n4) return;
    float4 v = ((const float4*)in)[i];
    __nv_bfloat16 h0 = __float2bfloat16(v.x), h1 = __float2bfloat16(v.y);
    __nv_bfloat16 h2 = __float2bfloat16(v.z), h3 = __float2bfloat16(v.w);
    __nv_bfloat16 l0 = __float2bfloat16(v.x - __bfloat162float(h0));
    __nv_bfloat16 l1 = __float2bfloat16(v.y - __bfloat162float(h1));
    __nv_bfloat16 l2 = __float2bfloat16(v.z - __bfloat162float(h2));
    __nv_bfloat16 l3 = __float2bfloat16(v.w - __bfloat162float(h3));
    ((__nv_bfloat162*)hi)[i * 2 + 0] = __nv_bfloat162(h0, h1);
    ((__nv_bfloat162*)hi)[i * 2 + 1] = __nv_bfloat162(h2, h3);
    ((__nv_bfloat162*)lo)[i * 2 + 0] = __nv_bfloat162(l0, l1);
    ((__nv_bfloat162*)lo)[i * 2 + 1] = __nv_bfloat162(l2, l3);
}

// ------ LayerNorm of q halves, fused split-K=4 reduction --------------------------
__global__ void qln_kernel(const float* __restrict__ q0, const float* __restrict__ q1,
                           const float* __restrict__ q2, const float* __restrict__ q3,
                           float* __restrict__ qln,
                           __nv_bfloat16* __restrict__ qhi, __nv_bfloat16* __restrict__ qlo)
{
    int w = (blockIdx.x * blockDim.x + threadIdx.x) >> 5;
    int lane = threadIdx.x & 31;
    if (w >= BS_N * 2) return;
    int half = w & 1, b = w >> 1;
    size_t base = (size_t)b * 512 + half * 256;
    float vals[8];
    float s = 0.f;
#pragma unroll
    for (int e = 0; e < 8; e++) {
        size_t idx = base + lane + 32 * e;
        vals[e] = (q0[idx] + q1[idx]) + (q2[idx] + q3[idx]);
        s += vals[e];
    }
#pragma unroll
    for (int off = 16; off; off >>= 1) s += __shfl_xor_sync(~0u, s, off);
    float mean = s * (1.f / 256.f);
    float vs = 0.f;
#pragma unroll
    for (int e = 0; e < 8; e++) { float d = vals[e] - mean; vs += d * d; }
#pragma unroll
    for (int off = 16; off; off >>= 1) vs += __shfl_xor_sync(~0u, vs, off);
    float scale = rsqrtf(vs * (1.f / 256.f) + 1e-5f) * GW;
#pragma unroll
    for (int e = 0; e < 8; e++) {
        float o = (vals[e] - mean) * scale;
        qln[base + lane + 32 * e] = o;
        __nv_bfloat16 h = __float2bfloat16(o);
        qhi[base + lane + 32 * e] = h;
        qlo[base + lane + 32 * e] = __float2bfloat16(o - __bfloat162float(h));
    }
}

// ------- fused key LayerNorm (r=0,1) + u/v contraction: one warp per (h,side,n) ---
__global__ void keynorm_knu_kernel(const float* __restrict__ keys,
                                   const float* __restrict__ u, const float* __restrict__ v,
                                   float* __restrict__ knw,
                                   __nv_bfloat16* __restrict__ khi,
                                   __nv_bfloat16* __restrict__ klo)
{
    int w = (blockIdx.x * blockDim.x + threadIdx.x) >> 5;   // 0..2047
    int lane = threadIdx.x & 31;
    if (w >= HEAD * 2 * KEY_NUM) return;
    int n    = w & (KEY_NUM - 1);
    int side = (w >> 9) & 1;
    int h    = w >> 10;
    const float* base = keys + (size_t)(((h * 2 + side) * KEY_NUM + n)) * KDIM * RANK;
    float v0[8], v1[8];
    float s0 = 0.f, s1 = 0.f;
#pragma unroll
    for (int e = 0; e < 8; e++) {
        float2 kv = *(const float2*)(base + (lane + 32 * e) * RANK);
        v0[e] = kv.x; v1[e] = kv.y; s0 += kv.x; s1 += kv.y;
    }
#pragma unroll
    for (int off = 16; off; off >>= 1) {
        s0 += __shfl_xor_sync(~0u, s0, off);
        s1 += __shfl_xor_sync(~0u, s1, off);
    }
    float m0 = s0 * (1.f / 256.f), m1 = s1 * (1.f / 256.f);
    float q0 = 0.f, q1 = 0.f;
#pragma unroll
    for (int e = 0; e < 8; e++) {
        float d0 = v0[e] - m0, d1 = v1[e] - m1;
        q0 += d0 * d0; q1 += d1 * d1;
    }
#pragma unroll
    for (int off = 16; off; off >>= 1) {
        q0 += __shfl_xor_sync(~0u, q0, off);
        q1 += __shfl_xor_sync(~0u, q1, off);
    }
    float sc0 = rsqrtf(q0 * (1.f / 256.f) + 1e-5f) * GW;
    float sc1 = rsqrtf(q1 * (1.f / 256.f) + 1e-5f) * GW;

    const float* coef = (side ? v : u) + h * RANK;
    float c0 = coef[0], c1 = coef[1];

    float* out0 = knw + ((size_t)side * 2048 + (size_t)(h * KEY_NUM + n) * 2) * KDIM;
    size_t gknu = ((size_t)side * 1024 + h * KEY_NUM + n) * KDIM;
#pragma unroll
    for (int e = 0; e < 8; e++) {
        int k = lane + 32 * e;
        float n0 = (v0[e] - m0) * sc0;
        float n1 = (v1[e] - m1) * sc1;
        out0[k] = n0;
        out0[KDIM + k] = n1;
        float val = n0 * c0 + n1 * c1;
        __nv_bfloat16 hh = __float2bfloat16(val);
        khi[gknu + k] = hh;
        klo[gknu + k] = __float2bfloat16(val - __bfloat162float(hh));
    }
}

// --- fused: top-16 (both sides) + gathered exact scores + tucker cand + softmax ---
// one warp per (b,h).
__global__ void cand_kernel(const float* __restrict__ a1, const float* __restrict__ a2,
                            const float* __restrict__ qln,
                            const float* __restrict__ knw,
                            const float* __restrict__ core0, const float* __restrict__ core1,
                            const int* __restrict__ shuffle_index,
                            int* __restrict__ vidx_out, float* __restrict__ w_out)
{
    int w = (blockIdx.x * blockDim.x + threadIdx.x) >> 5;
    int lane = threadIdx.x & 31;
    if (w >= BS_N * HEAD) return;
    int h = w & 1, b = w >> 1;

    // ---- top-16 per side (identical algorithm/tie-break as before) ----
    const float* ap1 = a1 + (size_t)b * 1024 + h * 512;
    const float* ap2 = a2 + (size_t)b * 1024 + h * 512;
    float av1[16], av2[16];
#pragma unroll
    for (int e = 0; e < 16; e++) { av1[e] = ap1[lane + 32 * e]; av2[e] = ap2[lane + 32 * e]; }

    int myn = 0;
#pragma unroll 1
    for (int t = 0; t < KNN; t++) {
        float bv = -FLT_MAX; int bi = 0x7fffffff;
#pragma unroll
        for (int e = 0; e < 16; e++) {
            int n = lane + 32 * e;
            if (av1[e] > bv) { bv = av1[e]; bi = n; }
        }
#pragma unroll
        for (int off = 16; off; off >>= 1) {
            float ov = __shfl_xor_sync(~0u, bv, off);
            int   oi = __shfl_xor_sync(~0u, bi, off);
            if (ov > bv || (ov == bv && oi < bi)) { bv = ov; bi = oi; }
        }
        if (lane == (bi & 31)) av1[bi >> 5] = -FLT_MAX;
        if (lane == t) myn = bi;
    }
#pragma unroll 1
    for (int t = 0; t < KNN; t++) {
        float bv = -FLT_MAX; int bi = 0x7fffffff;
#pragma unroll
        for (int e = 0; e < 16; e++) {
            int n = lane + 32 * e;
            if (av2[e] > bv) { bv = av2[e]; bi = n; }
        }
#pragma unroll
        for (int off = 16; off; off >>= 1) {
            float ov = __shfl_xor_sync(~0u, bv, off);
            int   oi = __shfl_xor_sync(~0u, bi, off);
            if (ov > bv || (ov == bv && oi < bi)) { bv = ov; bi = oi; }
        }
        if (lane == (bi & 31)) av2[bi >> 5] = -FLT_MAX;
        if (lane == 16 + t) myn = bi;
    }

    float C00 = core0[h * 4 + 0] + core1[h * 4 + 0];
    float C01 = core0[h * 4 + 1] + core1[h * 4 + 1];
    float C10 = core0[h * 4 + 2] + core1[h * 4 + 2];
    float C11 = core0[h * 4 + 3] + core1[h * 4 + 3];

    const float4* q1 = (const float4*)(qln + (size_t)b * 512);
    const float4* q2 = q1 + 64;
    const float4 q1a = q1[lane], q1b = q1[lane + 32];
    const float4 q2a = q2[lane], q2b = q2[lane + 32];

    const float* kbase0 = knw + (size_t)(h * KEY_NUM) * 2 * KDIM;
    const float* kbase1 = knw + (size_t)2048 * KDIM + (size_t)(h * KEY_NUM) * 2 * KDIM;

    float g0 = 0.f, g1 = 0.f;
#pragma unroll 2
    for (int r = 0; r < 32; r++) {
        int n = __shfl_sync(~0u, myn, r);
        const int side = r >> 4;
        const float4* kp = (const float4*)((side ? kbase1 : kbase0) + (size_t)n * 2 * KDIM);
        const float4 qa = side ? q2a : q1a;
        const float4 qb = side ? q2b : q1b;
        float4 k0a = kp[lane], k0b = kp[lane + 32];
        float4 k1a = kp[64 + lane], k1b = kp[64 + lane + 32];
        float p0 = qa.x * k0a.x + qa.y * k0a.y + qa.z * k0a.z + qa.w * k0a.w
                 + qb.x * k0b.x + qb.y * k0b.y + qb.z * k0b.z + qb.w * k0b.w;
        float p1 = qa.x * k1a.x + qa.y * k1a.y + qa.z * k1a.z + qa.w * k1a.w
                 + qb.x * k1b.x + qb.y * k1b.y + qb.z * k1b.z + qb.w * k1b.w;
#pragma unroll
        for (int off = 16; off; off >>= 1) {
            p0 += __shfl_xor_sync(~0u, p0, off);
            p1 += __shfl_xor_sync(~0u, p1, off);
        }
        if (lane == r) { g0 = p0; g1 = p1; }
    }
    __syncwarp();

    float t0  = g0 * C00 + g1 * C10;
    float t1v = g0 * C01 + g1 * C11;

    float cv[8];
#pragma unroll
    for (int c = 0; c < 8; c++) {
        int cid = lane * 8 + c;
        int i = cid >> 4, j = cid & 15;
        float ti0 = __shfl_sync(~0u, t0,  i);
        float ti1 = __shfl_sync(~0u, t1v, i);
        float sj0 = __shfl_sync(~0u, g0, 16 + j);
        float sj1 = __shfl_sync(~0u, g1, 16 + j);
        cv[c] = ti0 * sj0 + ti1 * sj1;
    }

    float selv = 0.f; int selc = 0;
#pragma unroll 1
    for (int t = 0; t < KNN; t++) {
        float bv = -FLT_MAX; int bc = 0x7fffffff;
#pragma unroll
        for (int c = 0; c < 8; c++) {
            int cid = lane * 8 + c;
            if (cv[c] > bv) { bv = cv[c]; bc = cid; }
        }
#pragma unroll
        for (int off = 16; off; off >>= 1) {
            float ov = __shfl_xor_sync(~0u, bv, off);
            int   oc = __shfl_xor_sync(~0u, bc, off);
            if (ov > bv || (ov == bv && oc < bc)) { bv = ov; bc = oc; }
        }
        if (lane == (bc >> 3)) cv[bc & 7] = -FLT_MAX;
        if (lane == t) { selv = bv; selc = bc; }
    }

    float mx = __shfl_sync(~0u, selv, 0);
    float e = (lane < KNN) ? expf(selv - mx) : 0.f;
    float sum = e;
#pragma unroll
    for (int off = 16; off; off >>= 1) sum += __shfl_xor_sync(~0u, sum, off);
    float wgt = e / sum;

    int ii = (selc >> 4) & 15, jj = selc & 15;
    int key_i = __shfl_sync(~0u, myn, ii);
    int key_j = __shfl_sync(~0u, myn, 16 + jj);
    if (lane < KNN) {
        int vi = shuffle_index[key_i * KEY_NUM + key_j];
        vidx_out[(b * HEAD + h) * KNN + lane] = vi;
        w_out  [(b * HEAD + h) * KNN + lane] = wgt;
    }
}

// ------- sparse gather + weighted combine -> bf16 hi/lo out_v ---------------------
__global__ __launch_bounds__(128) void gather_kernel(
    const float* __restrict__ values, const int* __restrict__ vidx,
    const float* __restrict__ wgt,
    __nv_bfloat16* __restrict__ ovhi, __nv_bfloat16* __restrict__ ovlo)
{
    int b = blockIdx.x;
    __shared__ int   sidx[HEAD * KNN];
    __shared__ float sw[HEAD * KNN];
    if (threadIdx.x < HEAD * KNN) {
        sidx[threadIdx.x] = vidx[b * HEAD * KNN + threadIdx.x];
        sw[threadIdx.x]   = wgt [b * HEAD * KNN + threadIdx.x];
    }
    __syncthreads();
    int d = threadIdx.x * 4;
    float4 acc = make_float4(0.f, 0.f, 0.f, 0.f);
#pragma unroll
    for (int t = 0; t < HEAD * KNN; t++) {
        const float4 v = *(const float4*)(values + (size_t)sidx[t] * VDIM + d);
        float ww = sw[t];
        acc.x = fmaf(ww, v.x, acc.x);
        acc.y = fmaf(ww, v.y, acc.y);
        acc.z = fmaf(ww, v.z, acc.z);
        acc.w = fmaf(ww, v.w, acc.w);
    }
    size_t ob = (size_t)b * VDIM + d;
    __nv_bfloat16 h0 = __float2bfloat16(acc.x), h1 = __float2bfloat16(acc.y);
    __nv_bfloat16 h2 = __float2bfloat16(acc.z), h3 = __float2bfloat16(acc.w);
    ((__nv_bfloat162*)(ovhi + ob))[0] = __nv_bfloat162(h0, h1);
    ((__nv_bfloat162*)(ovhi + ob))[1] = __nv_bfloat162(h2, h3);
    ((__nv_bfloat162*)(ovlo + ob))[0] =
        __nv_bfloat162(__float2bfloat16(acc.x - __bfloat162float(h0)),
                       __float2bfloat16(acc.y - __bfloat162float(h1)));
    ((__nv_bfloat162*)(ovlo + ob))[1] =
        __nv_bfloat162(__float2bfloat16(acc.z - __bfloat162float(h2)),
                       __float2bfloat16(acc.w - __bfloat162float(h3)));
}

// -------------------------------- launcher ----------------------------------------
extern "C" void kernel_launch(void* const* d_in, const int* in_sizes, int n_in,
                              void* d_out, int out_size)
{
    const float* x        = (const float*)d_in[0];
    const float* q_proj_w = (const float*)d_in[1];
    const float* keys     = (const float*)d_in[2];
    const float* core0    = (const float*)d_in[3];
    const float* core1    = (const float*)d_in[4];
    const float* u        = (const float*)d_in[5];
    const float* v        = (const float*)d_in[6];
    const float* values   = (const float*)d_in[7];
    const float* vproj_w  = (const float*)d_in[8];
    const int*   shuffle  = (const int*)d_in[9];
    float*       out      = (float*)d_out;

    float *p_q, *p_qln, *p_knw, *p_a, *p_w;
    int *p_vidx;
    __nv_bfloat16 *xhi, *xlo, *wqhi, *wqlo, *qlnhi, *qlnlo, *knuhi, *knulo;
    __nv_bfloat16 *ovhi, *ovlo, *vphi, *vplo;
    cudaGetSymbolAddress((void**)&p_q,    g_q);
    cudaGetSymbolAddress((void**)&p_qln,  g_qln);
    cudaGetSymbolAddress((void**)&p_knw,  g_knw);
    cudaGetSymbolAddress((void**)&p_a,    g_a);
    cudaGetSymbolAddress((void**)&p_vidx, g_vidx);
    cudaGetSymbolAddress((void**)&p_w,    g_w);
    cudaGetSymbolAddress((void**)&xhi,    g_xhi);
    cudaGetSymbolAddress((void**)&xlo,    g_xlo);
    cudaGetSymbolAddress((void**)&wqhi,   g_wqhi);
    cudaGetSymbolAddress((void**)&wqlo,   g_wqlo);
    cudaGetSymbolAddress((void**)&qlnhi,  g_qlnhi);
    cudaGetSymbolAddress((void**)&qlnlo,  g_qlnlo);
    cudaGetSymbolAddress((void**)&knuhi,  g_knuhi);
    cudaGetSymbolAddress((void**)&knulo,  g_knulo);
    cudaGetSymbolAddress((void**)&ovhi,   g_ovhi);
    cudaGetSymbolAddress((void**)&ovlo,   g_ovlo);
    cudaGetSymbolAddress((void**)&vphi,   g_vphi);
    cudaGetSymbolAddress((void**)&vplo,   g_vplo);

    float* q0 = p_q;
    float* q1p = p_q + (size_t)BS_N * 512;
    float* q2p = p_q + (size_t)2 * BS_N * 512;
    float* q3p = p_q + (size_t)3 * BS_N * 512;
    float* a1 = p_a;
    float* a2 = p_a + (size_t)BS_N * HEAD * KEY_NUM;

    constexpr int STAGE64 = 2 * 64 * ROW_B + 2 * 128 * ROW_B;        // 24576
    constexpr int SMEM64  = 3 * STAGE64;                             // 73728
    cudaFuncSetAttribute(mma_gemm, cudaFuncAttributeMaxDynamicSharedMemorySize, SMEM64);

    // 0) fp32 -> bf16 hi/lo splits of static GEMM operands
    conv_kernel<<<(BS_N * HID / 4) / 256, 256>>>(x, xhi, xlo, BS_N * HID / 4);
    conv_kernel<<<(2 * KDIM * HID / 4) / 256, 256>>>(q_proj_w, wqhi, wqlo, 2 * KDIM * HID / 4);
    conv_kernel<<<(HID * VDIM / 4) / 256, 256>>>(vproj_w, vphi, vplo, HID * VDIM / 4);

    // 1) q = x @ Wq^T  [4096 x 512], K=2048, split-K=4 -> partials q0..q3
    mma_gemm<<<dim3(512 / 128, BS_N / 64, 4), 128, SMEM64>>>(
        xhi, xlo, wqhi, wqlo, q0, HID, HID, 512, 512 / 32,
        512, 512, 0, (long long)BS_N * 512);

    // 2) per-half LayerNorm of q (fused split-K=4 reduction; fp32 + bf16 hi/lo)
    qln_kernel<<<(BS_N * 2 * 32) / 256, 256>>>(q0, q1p, q2p, q3p, p_qln, qlnhi, qlnlo);

    // 3) fused key LayerNorm + u/v contraction
    keynorm_knu_kernel<<<(HEAD * 2 * KEY_NUM * 32) / 256, 256>>>(
        keys, u, v, p_knw, knuhi, knulo);

    // 4) approx scores a = qln_half @ knu_side^T  [4096 x 1024], K=256, z=side
    mma_gemm<<<dim3(1024 / 128, BS_N / 64, 2), 128, SMEM64>>>(
        qlnhi, qlnlo, knuhi, knulo, p_a, 512, KDIM, 1024, KDIM / 32,
        256, 0, 1024, (long long)BS_N * 1024);

    // 5) fused top-16 (both sides) + exact tucker candidates + softmax + vidx
    cand_kernel<<<(BS_N * HEAD * 32) / 256, 256>>>(a1, a2, p_qln, p_knw,
                                                   core0, core1, shuffle, p_vidx, p_w);

    // 6) sparse gather + weighted combine -> bf16 hi/lo out_v [4096 x 512]
    gather_kernel<<<BS_N, 128>>>(values, p_vidx, p_w, ovhi, ovlo);

    // 7) out = out_v @ vproj_w^T  [4096 x 2048], K=512 (16 chunks)
    mma_gemm<<<dim3(2048 / 128, BS_N / 64, 1), 128, SMEM64>>>(
        ovhi, ovlo, vphi, vplo, out, VDIM, VDIM, 2048, VDIM / 32,
        0, 0, 0, 0LL);
}

// round 14
// speedup vs baseline: 1.0691x; 1.0691x over previous
#include <cuda_runtime.h>
#include <cuda_bf16.h>
#include <cfloat>
#include <math.h>
#include <stdint.h>

#define BS_N    4096
#define HID     2048
#define KDIM    256
#define KEY_NUM 512
#define HEAD    2
#define RANK    2
#define KNN     16
#define VDIM    512

// G = KDIM^-0.4 = 256^-0.4 = 2^-3.2
#define GW      0.10881882041201557f

// ---------------- scratch (device globals; no runtime allocation) ----------------
__device__ __align__(256) float g_q   [4][BS_N * 2 * KDIM]; // split-K partials
__device__ __align__(256) float g_qln [BS_N * 2 * KDIM];
__device__ __align__(256) float g_knw [HEAD * 2 * KEY_NUM * RANK * KDIM];
__device__ __align__(256) float g_a   [2][BS_N * HEAD * KEY_NUM];
__device__ int   g_vidx[BS_N * HEAD * KNN];
__device__ float g_w   [BS_N * HEAD * KNN];

// bf16 hi/lo split operands for tensor-core GEMMs
__device__ __align__(256) __nv_bfloat16 g_xhi [BS_N * HID];
__device__ __align__(256) __nv_bfloat16 g_xlo [BS_N * HID];
__device__ __align__(256) __nv_bfloat16 g_wqhi[2 * KDIM * HID];
__device__ __align__(256) __nv_bfloat16 g_wqlo[2 * KDIM * HID];
__device__ __align__(256) __nv_bfloat16 g_qlnhi[BS_N * 2 * KDIM];
__device__ __align__(256) __nv_bfloat16 g_qlnlo[BS_N * 2 * KDIM];
__device__ __align__(256) __nv_bfloat16 g_knuhi[2 * HEAD * KEY_NUM * KDIM];
__device__ __align__(256) __nv_bfloat16 g_knulo[2 * HEAD * KEY_NUM * KDIM];
__device__ __align__(256) __nv_bfloat16 g_ovhi[BS_N * VDIM];
__device__ __align__(256) __nv_bfloat16 g_ovlo[BS_N * VDIM];
__device__ __align__(256) __nv_bfloat16 g_vphi[HID * VDIM];
__device__ __align__(256) __nv_bfloat16 g_vplo[HID * VDIM];

// ================================ PTX helpers =====================================
__device__ __forceinline__ uint32_t smem_u32(const void* p) {
    return (uint32_t)__cvta_generic_to_shared(p);
}
__device__ __forceinline__ void cp16(uint32_t s, const void* g) {
    asm volatile("cp.async.cg.shared.global [%0], [%1], 16;" :: "r"(s), "l"(g) : "memory");
}
__device__ __forceinline__ void ldsm_x4(uint32_t& r0, uint32_t& r1, uint32_t& r2, uint32_t& r3,
                                        uint32_t addr) {
    asm volatile("ldmatrix.sync.aligned.m8n8.x4.shared.b16 {%0,%1,%2,%3}, [%4];"
                 : "=r"(r0), "=r"(r1), "=r"(r2), "=r"(r3) : "r"(addr));
}
__device__ __forceinline__ void mma16816(float* d, const uint32_t* a, uint32_t b0, uint32_t b1) {
    asm volatile(
        "mma.sync.aligned.m16n8k16.row.col.f32.bf16.bf16.f32 "
        "{%0,%1,%2,%3}, {%4,%5,%6,%7}, {%8,%9}, {%0,%1,%2,%3};"
        : "+f"(d[0]), "+f"(d[1]), "+f"(d[2]), "+f"(d[3])
        : "r"(a[0]), "r"(a[1]), "r"(a[2]), "r"(a[3]), "r"(b0), "r"(b1));
}

// SMEM tile geometry: rows x 32 bf16 = 64 B/row, XOR-swizzled 16B chunks.
// Bank-group position of (row,chunk) = (4*(row&1) + (chunk ^ ((row>>1)&3))) mod 8
// -> conflict-free for ldmatrix 8-row phases and cp.async 2-row x 4-chunk phases.
#define ROW_B 64
__device__ __forceinline__ uint32_t swz(int row, int chunk) {
    return (uint32_t)(row * ROW_B + ((chunk ^ ((row >> 1) & 3)) << 4));
}

// ============ bf16-split tensor-core GEMM:  C[M,N] = A[M,K] * B[N,K]^T (fp32) =====
// CTA tile 64 x 128, BK=32, 8 warps (2m x 4n, warp tile 32x32), cp.async 3-stage
// pipeline, XOR-swizzled smem, 3-term hi/lo split accumulated in fp32. 3 CTAs/SM.
__global__ __launch_bounds__(256, 3) void mma_gemm(
    const __nv_bfloat16* __restrict__ Ahi, const __nv_bfloat16* __restrict__ Alo,
    const __nv_bfloat16* __restrict__ Bhi, const __nv_bfloat16* __restrict__ Blo,
    float* __restrict__ C, int lda, int ldb, int ldc, int nchunks,
    int a_koff_z, int b_koff_z, int b_noff_z, long long c_off_z)
{
    constexpr int BM     = 64;
    constexpr int NW_M   = 2;
    constexpr int WTN    = 32;             // warp tile n
    constexpr int FN     = 4;              // n8 frags
    constexpr int TILE_A = BM * ROW_B;     // 4096
    constexpr int TILE_B2 = 128 * ROW_B;   // 8192
    constexpr int STAGE  = 2 * TILE_A + 2 * TILE_B2;  // 24576

    extern __shared__ __align__(256) char smem[];
    const uint32_t sb = smem_u32(smem);
    const int t = threadIdx.x;
    const int wid = t >> 5, lane = t & 31;
    const int m0 = blockIdx.y * BM;
    const int nb = blockIdx.x * 128 + blockIdx.z * b_noff_z;  // B row base
    const int n0 = blockIdx.x * 128;                          // C col base
    const int aK0 = blockIdx.z * a_koff_z;
    const int bK0 = blockIdx.z * b_koff_z;
    C += (long long)blockIdx.z * c_off_z;

    const int wm = wid % NW_M;
    const int wn = wid / NW_M;

    // ldmatrix lane geometry
    const int lm_row = (lane & 7) + ((lane >> 3) & 1) * 8;   // 0..15
    const int cbase = lane >> 4;                              // 0 or 1

    float acc[2][FN][4] = {};

    auto load_stage = [&](int i, int buf) {
        const uint32_t sbuf = sb + (uint32_t)buf * STAGE;
        const int kA = aK0 + i * 32;
        const int kB = bK0 + i * 32;
        {
            const int row = t >> 2, c = t & 3;
            const uint32_t so = swz(row, c);
            cp16(sbuf +          so, Ahi + (size_t)(m0 + row) * lda + kA + c * 8);
            cp16(sbuf + TILE_A + so, Alo + (size_t)(m0 + row) * lda + kA + c * 8);
        }
#pragma unroll
        for (int rep = 0; rep < 2; rep++) {
            const int idx = t + rep * 256;
            const int row = idx >> 2, c = idx & 3;
            const uint32_t so = swz(row, c);
            cp16(sbuf + 2 * TILE_A +           so, Bhi + (size_t)(nb + row) * ldb + kB + c * 8);
            cp16(sbuf + 2 * TILE_A + TILE_B2 + so, Blo + (size_t)(nb + row) * ldb + kB + c * 8);
        }
        asm volatile("cp.async.commit_group;" ::: "memory");
    };

    auto compute_stage = [&](int buf) {
        const uint32_t sbuf = sb + (uint32_t)buf * STAGE;
        const uint32_t sAhi = sbuf;
        const uint32_t sAlo = sbuf + TILE_A;
        const uint32_t sBhi = sbuf + 2 * TILE_A;
        const uint32_t sBlo = sbuf + 2 * TILE_A + TILE_B2;
#pragma unroll
        for (int kh = 0; kh < 2; kh++) {
            const int chunk = cbase + kh * 2;
            uint32_t ah[2][4], al[2][4];
#pragma unroll
            for (int fm = 0; fm < 2; fm++) {
                const int row = wm * 32 + fm * 16 + lm_row;
                const uint32_t ro = swz(row, chunk);
                ldsm_x4(ah[fm][0], ah[fm][1], ah[fm][2], ah[fm][3], sAhi + ro);
                ldsm_x4(al[fm][0], al[fm][1], al[fm][2], al[fm][3], sAlo + ro);
            }
#pragma unroll
            for (int f = 0; f < FN / 2; f++) {       // each f covers n16
                const int row = wn * WTN + f * 16 + lm_row;
                const uint32_t ro = swz(row, chunk);
                uint32_t h0, h1, h2, h3, l0, l1, l2, l3;
                ldsm_x4(h0, h1, h2, h3, sBhi + ro);
                ldsm_x4(l0, l1, l2, l3, sBlo + ro);
                // term-major: 4 distinct accs per term; per-acc order hh->hl->lh
                mma16816(acc[0][f * 2],     ah[0], h0, h2);
                mma16816(acc[0][f * 2 + 1], ah[0], h1, h3);
                mma16816(acc[1][f * 2],     ah[1], h0, h2);
                mma16816(acc[1][f * 2 + 1], ah[1], h1, h3);
                mma16816(acc[0][f * 2],     ah[0], l0, l2);
                mma16816(acc[0][f * 2 + 1], ah[0], l1, l3);
                mma16816(acc[1][f * 2],     ah[1], l0, l2);
                mma16816(acc[1][f * 2 + 1], ah[1], l1, l3);
                mma16816(acc[0][f * 2],     al[0], h0, h2);
                mma16816(acc[0][f * 2 + 1], al[0], h1, h3);
                mma16816(acc[1][f * 2],     al[1], h0, h2);
                mma16816(acc[1][f * 2 + 1], al[1], h1, h3);
            }
        }
    };

    // 3-stage pipeline: two-ahead prefetch; iteration-top sync gates slot reuse.
    load_stage(0, 0);
    if (nchunks > 1) load_stage(1, 1);
    for (int i = 0; i < nchunks; i++) {
        if (i + 1 < nchunks) {
            asm volatile("cp.async.wait_group 1;" ::: "memory");
        } else {
            asm volatile("cp.async.wait_group 0;" ::: "memory");
        }
        __syncthreads();
        if (i + 2 < nchunks) load_stage(i + 2, (i + 2) % 3);
        compute_stage(i % 3);
    }

    // ---- epilogue: direct fp32 stores ----
    const int er = lane >> 2, ec = (lane & 3) * 2;
#pragma unroll
    for (int fm = 0; fm < 2; fm++) {
        const int row = m0 + wm * 32 + fm * 16 + er;
#pragma unroll
        for (int fn = 0; fn < FN; fn++) {
            const int col = n0 + wn * WTN + fn * 8 + ec;
            *(float2*)(C + (size_t)row * ldc + col) =
                make_float2(acc[fm][fn][0], acc[fm][fn][1]);
            *(float2*)(C + (size_t)(row + 8) * ldc + col) =
                make_float2(acc[fm][fn][2], acc[fm][fn][3]);
        }
    }
}

// ---------------- fp32 -> (bf16 hi, bf16 lo) elementwise split --------------------
__global__ void conv_kernel(const float* __restrict__ in,
                            __nv_bfloat16* __restrict__ hi, __nv_bfloat16* __restrict__ lo,
                            int n4)
{
    int i = blockIdx.x * blockDim.x + threadIdx.x;
    if (i >= n4) return;
    float4 v = ((const float4*)in)[i];
    __nv_bfloat16 h0 = __float2bfloat16(v.x), h1 = __float2bfloat16(v.y);
    __nv_bfloat16 h2 = __float2bfloat16(v.z), h3 = __float2bfloat16(v.w);
    __nv_bfloat16 l0 = __float2bfloat16(v.x - __bfloat162float(h0));
    __nv_bfloat16 l1 = __float2bfloat16(v.y - __bfloat162float(h1));
    __nv_bfloat16 l2 = __float2bfloat16(v.z - __bfloat162float(h2));
    __nv_bfloat16 l3 = __float2bfloat16(v.w - __bfloat162float(h3));
    ((__nv_bfloat162*)hi)[i * 2 + 0] = __nv_bfloat162(h0, h1);
    ((__nv_bfloat162*)hi)[i * 2 + 1] = __nv_bfloat162(h2, h3);
    ((__nv_bfloat162*)lo)[i * 2 + 0] = __nv_bfloat162(l0, l1);
    ((__nv_bfloat162*)lo)[i * 2 + 1] = __nv_bfloat162(l2, l3);
}

// ------ LayerNorm of q halves, fused split-K=4 reduction --------------------------
__global__ void qln_kernel(const float* __restrict__ q0, const float* __restrict__ q1,
                           const float* __restrict__ q2, const float* __restrict__ q3,
                           float* __restrict__ qln,
                           __nv_bfloat16* __restrict__ qhi, __nv_bfloat16* __restrict__ qlo)
{
    int w = (blockIdx.x * blockDim.x + threadIdx.x) >> 5;
    int lane = threadIdx.x & 31;
    if (w >= BS_N * 2) return;
    int half = w & 1, b = w >> 1;
    size_t base = (size_t)b * 512 + half * 256;
    float vals[8];
    float s = 0.f;
#pragma unroll
    for (int e = 0; e < 8; e++) {
        size_t idx = base + lane + 32 * e;
        vals[e] = (q0[idx] + q1[idx]) + (q2[idx] + q3[idx]);
        s += vals[e];
    }
#pragma unroll
    for (int off = 16; off; off >>= 1) s += __shfl_xor_sync(~0u, s, off);
    float mean = s * (1.f / 256.f);
    float vs = 0.f;
#pragma unroll
    for (int e = 0; e < 8; e++) { float d = vals[e] - mean; vs += d * d; }
#pragma unroll
    for (int off = 16; off; off >>= 1) vs += __shfl_xor_sync(~0u, vs, off);
    float scale = rsqrtf(vs * (1.f / 256.f) + 1e-5f) * GW;
#pragma unroll
    for (int e = 0; e < 8; e++) {
        float o = (vals[e] - mean) * scale;
        qln[base + lane + 32 * e] = o;
        __nv_bfloat16 h = __float2bfloat16(o);
        qhi[base + lane + 32 * e] = h;
        qlo[base + lane + 32 * e] = __float2bfloat16(o - __bfloat162float(h));
    }
}

// ------- fused key LayerNorm (r=0,1) + u/v contraction: one warp per (h,side,n) ---
__global__ void keynorm_knu_kernel(const float* __restrict__ keys,
                                   const float* __restrict__ u, const float* __restrict__ v,
                                   float* __restrict__ knw,
                                   __nv_bfloat16* __restrict__ khi,
                                   __nv_bfloat16* __restrict__ klo)
{
    int w = (blockIdx.x * blockDim.x + threadIdx.x) >> 5;   // 0..2047
    int lane = threadIdx.x & 31;
    if (w >= HEAD * 2 * KEY_NUM) return;
    int n    = w & (KEY_NUM - 1);
    int side = (w >> 9) & 1;
    int h    = w >> 10;
    const float* base = keys + (size_t)(((h * 2 + side) * KEY_NUM + n)) * KDIM * RANK;
    float v0[8], v1[8];
    float s0 = 0.f, s1 = 0.f;
#pragma unroll
    for (int e = 0; e < 8; e++) {
        float2 kv = *(const float2*)(base + (lane + 32 * e) * RANK);
        v0[e] = kv.x; v1[e] = kv.y; s0 += kv.x; s1 += kv.y;
    }
#pragma unroll
    for (int off = 16; off; off >>= 1) {
        s0 += __shfl_xor_sync(~0u, s0, off);
        s1 += __shfl_xor_sync(~0u, s1, off);
    }
    float m0 = s0 * (1.f / 256.f), m1 = s1 * (1.f / 256.f);
    float q0 = 0.f, q1 = 0.f;
#pragma unroll
    for (int e = 0; e < 8; e++) {
        float d0 = v0[e] - m0, d1 = v1[e] - m1;
        q0 += d0 * d0; q1 += d1 * d1;
    }
#pragma unroll
    for (int off = 16; off; off >>= 1) {
        q0 += __shfl_xor_sync(~0u, q0, off);
        q1 += __shfl_xor_sync(~0u, q1, off);
    }
    float sc0 = rsqrtf(q0 * (1.f / 256.f) + 1e-5f) * GW;
    float sc1 = rsqrtf(q1 * (1.f / 256.f) + 1e-5f) * GW;

    const float* coef = (side ? v : u) + h * RANK;
    float c0 = coef[0], c1 = coef[1];

    float* out0 = knw + ((size_t)side * 2048 + (size_t)(h * KEY_NUM + n) * 2) * KDIM;
    size_t gknu = ((size_t)side * 1024 + h * KEY_NUM + n) * KDIM;
#pragma unroll
    for (int e = 0; e < 8; e++) {
        int k = lane + 32 * e;
        float n0 = (v0[e] - m0) * sc0;
        float n1 = (v1[e] - m1) * sc1;
        out0[k] = n0;
        out0[KDIM + k] = n1;
        float val = n0 * c0 + n1 * c1;
        __nv_bfloat16 hh = __float2bfloat16(val);
        khi[gknu + k] = hh;
        klo[gknu + k] = __float2bfloat16(val - __bfloat162float(hh));
    }
}

// --- fused: top-16 (both sides) + gathered exact scores + tucker cand + softmax ---
// one warp per (b,h); b ranges over [b0, b0+nb).
__global__ void cand_kernel(const float* __restrict__ a1, const float* __restrict__ a2,
                            const float* __restrict__ qln,
                            const float* __restrict__ knw,
                            const float* __restrict__ core0, const float* __restrict__ core1,
                            const int* __restrict__ shuffle_index,
                            int* __restrict__ vidx_out, float* __restrict__ w_out, int b0)
{
    int w = (blockIdx.x * blockDim.x + threadIdx.x) >> 5;
    int lane = threadIdx.x & 31;
    int h = w & 1, b = (w >> 1) + b0;

    // ---- top-16 per side (identical algorithm/tie-break as before) ----
    const float* ap1 = a1 + (size_t)b * 1024 + h * 512;
    const float* ap2 = a2 + (size_t)b * 1024 + h * 512;
    float av1[16], av2[16];
#pragma unroll
    for (int e = 0; e < 16; e++) { av1[e] = ap1[lane + 32 * e]; av2[e] = ap2[lane + 32 * e]; }

    int myn = 0;
#pragma unroll 1
    for (int t = 0; t < KNN; t++) {
        float bv = -FLT_MAX; int bi = 0x7fffffff;
#pragma unroll
        for (int e = 0; e < 16; e++) {
            int n = lane + 32 * e;
            if (av1[e] > bv) { bv = av1[e]; bi = n; }
        }
#pragma unroll
        for (int off = 16; off; off >>= 1) {
            float ov = __shfl_xor_sync(~0u, bv, off);
            int   oi = __shfl_xor_sync(~0u, bi, off);
            if (ov > bv || (ov == bv && oi < bi)) { bv = ov; bi = oi; }
        }
        if (lane == (bi & 31)) av1[bi >> 5] = -FLT_MAX;
        if (lane == t) myn = bi;
    }
#pragma unroll 1
    for (int t = 0; t < KNN; t++) {
        float bv = -FLT_MAX; int bi = 0x7fffffff;
#pragma unroll
        for (int e = 0; e < 16; e++) {
            int n = lane + 32 * e;
            if (av2[e] > bv) { bv = av2[e]; bi = n; }
        }
#pragma unroll
        for (int off = 16; off; off >>= 1) {
            float ov = __shfl_xor_sync(~0u, bv, off);
            int   oi = __shfl_xor_sync(~0u, bi, off);
            if (ov > bv || (ov == bv && oi < bi)) { bv = ov; bi = oi; }
        }
        if (lane == (bi & 31)) av2[bi >> 5] = -FLT_MAX;
        if (lane == 16 + t) myn = bi;
    }

    float C00 = core0[h * 4 + 0] + core1[h * 4 + 0];
    float C01 = core0[h * 4 + 1] + core1[h * 4 + 1];
    float C10 = core0[h * 4 + 2] + core1[h * 4 + 2];
    float C11 = core0[h * 4 + 3] + core1[h * 4 + 3];

    const float4* q1 = (const float4*)(qln + (size_t)b * 512);
    const float4* q2 = q1 + 64;
    const float4 q1a = q1[lane], q1b = q1[lane + 32];
    const float4 q2a = q2[lane], q2b = q2[lane + 32];

    const float* kbase0 = knw + (size_t)(h * KEY_NUM) * 2 * KDIM;
    const float* kbase1 = knw + (size_t)2048 * KDIM + (size_t)(h * KEY_NUM) * 2 * KDIM;

    float g0 = 0.f, g1 = 0.f;
#pragma unroll 2
    for (int r = 0; r < 32; r++) {
        int n = __shfl_sync(~0u, myn, r);
        const int side = r >> 4;
        const float4* kp = (const float4*)((side ? kbase1 : kbase0) + (size_t)n * 2 * KDIM);
        const float4 qa = side ? q2a : q1a;
        const float4 qb = side ? q2b : q1b;
        float4 k0a = kp[lane], k0b = kp[lane + 32];
        float4 k1a = kp[64 + lane], k1b = kp[64 + lane + 32];
        float p0 = qa.x * k0a.x + qa.y * k0a.y + qa.z * k0a.z + qa.w * k0a.w
                 + qb.x * k0b.x + qb.y * k0b.y + qb.z * k0b.z + qb.w * k0b.w;
        float p1 = qa.x * k1a.x + qa.y * k1a.y + qa.z * k1a.z + qa.w * k1a.w
                 + qb.x * k1b.x + qb.y * k1b.y + qb.z * k1b.z + qb.w * k1b.w;
#pragma unroll
        for (int off = 16; off; off >>= 1) {
            p0 += __shfl_xor_sync(~0u, p0, off);
            p1 += __shfl_xor_sync(~0u, p1, off);
        }
        if (lane == r) { g0 = p0; g1 = p1; }
    }
    __syncwarp();

    float t0  = g0 * C00 + g1 * C10;
    float t1v = g0 * C01 + g1 * C11;

    float cv[8];
#pragma unroll
    for (int c = 0; c < 8; c++) {
        int cid = lane * 8 + c;
        int i = cid >> 4, j = cid & 15;
        float ti0 = __shfl_sync(~0u, t0,  i);
        float ti1 = __shfl_sync(~0u, t1v, i);
        float sj0 = __shfl_sync(~0u, g0, 16 + j);
        float sj1 = __shfl_sync(~0u, g1, 16 + j);
        cv[c] = ti0 * sj0 + ti1 * sj1;
    }

    float selv = 0.f; int selc = 0;
#pragma unroll 1
    for (int t = 0; t < KNN; t++) {
        float bv = -FLT_MAX; int bc = 0x7fffffff;
#pragma unroll
        for (int c = 0; c < 8; c++) {
            int cid = lane * 8 + c;
            if (cv[c] > bv) { bv = cv[c]; bc = cid; }
        }
#pragma unroll
        for (int off = 16; off; off >>= 1) {
            float ov = __shfl_xor_sync(~0u, bv, off);
            int   oc = __shfl_xor_sync(~0u, bc, off);
            if (ov > bv || (ov == bv && oc < bc)) { bv = ov; bc = oc; }
        }
        if (lane == (bc >> 3)) cv[bc & 7] = -FLT_MAX;
        if (lane == t) { selv = bv; selc = bc; }
    }

    float mx = __shfl_sync(~0u, selv, 0);
    float e = (lane < KNN) ? expf(selv - mx) : 0.f;
    float sum = e;
#pragma unroll
    for (int off = 16; off; off >>= 1) sum += __shfl_xor_sync(~0u, sum, off);
    float wgt = e / sum;

    int ii = (selc >> 4) & 15, jj = selc & 15;
    int key_i = __shfl_sync(~0u, myn, ii);
    int key_j = __shfl_sync(~0u, myn, 16 + jj);
    if (lane < KNN) {
        int vi = shuffle_index[key_i * KEY_NUM + key_j];
        vidx_out[(b * HEAD + h) * KNN + lane] = vi;
        w_out  [(b * HEAD + h) * KNN + lane] = wgt;
    }
}

// ------- sparse gather + weighted combine -> bf16 hi/lo out_v ---------------------
__global__ __launch_bounds__(128) void gather_kernel(
    const float* __restrict__ values, const int* __restrict__ vidx,
    const float* __restrict__ wgt,
    __nv_bfloat16* __restrict__ ovhi, __nv_bfloat16* __restrict__ ovlo, int b0)
{
    int b = blockIdx.x + b0;
    __shared__ int   sidx[HEAD * KNN];
    __shared__ float sw[HEAD * KNN];
    if (threadIdx.x < HEAD * KNN) {
        sidx[threadIdx.x] = vidx[b * HEAD * KNN + threadIdx.x];
        sw[threadIdx.x]   = wgt [b * HEAD * KNN + threadIdx.x];
    }
    __syncthreads();
    int d = threadIdx.x * 4;
    float4 acc = make_float4(0.f, 0.f, 0.f, 0.f);
#pragma unroll
    for (int t = 0; t < HEAD * KNN; t++) {
        const float4 v = *(const float4*)(values + (size_t)sidx[t] * VDIM + d);
        float ww = sw[t];
        acc.x = fmaf(ww, v.x, acc.x);
        acc.y = fmaf(ww, v.y, acc.y);
        acc.z = fmaf(ww, v.z, acc.z);
        acc.w = fmaf(ww, v.w, acc.w);
    }
    size_t ob = (size_t)b * VDIM + d;
    __nv_bfloat16 h0 = __float2bfloat16(acc.x), h1 = __float2bfloat16(acc.y);
    __nv_bfloat16 h2 = __float2bfloat16(acc.z), h3 = __float2bfloat16(acc.w);
    ((__nv_bfloat162*)(ovhi + ob))[0] = __nv_bfloat162(h0, h1);
    ((__nv_bfloat162*)(ovhi + ob))[1] = __nv_bfloat162(h2, h3);
    ((__nv_bfloat162*)(ovlo + ob))[0] =
        __nv_bfloat162(__float2bfloat16(acc.x - __bfloat162float(h0)),
                       __float2bfloat16(acc.y - __bfloat162float(h1)));
    ((__nv_bfloat162*)(ovlo + ob))[1] =
        __nv_bfloat162(__float2bfloat16(acc.z - __bfloat162float(h2)),
                       __float2bfloat16(acc.w - __bfloat162float(h3)));
}

// -------------------------------- launcher ----------------------------------------
extern "C" void kernel_launch(void* const* d_in, const int* in_sizes, int n_in,
                              void* d_out, int out_size)
{
    const float* x        = (const float*)d_in[0];
    const float* q_proj_w = (const float*)d_in[1];
    const float* keys     = (const float*)d_in[2];
    const float* core0    = (const float*)d_in[3];
    const float* core1    = (const float*)d_in[4];
    const float* u        = (const float*)d_in[5];
    const float* v        = (const float*)d_in[6];
    const float* values   = (const float*)d_in[7];
    const float* vproj_w  = (const float*)d_in[8];
    const int*   shuffle  = (const int*)d_in[9];
    float*       out      = (float*)d_out;

    float *p_q, *p_qln, *p_knw, *p_a, *p_w;
    int *p_vidx;
    __nv_bfloat16 *xhi, *xlo, *wqhi, *wqlo, *qlnhi, *qlnlo, *knuhi, *knulo;
    __nv_bfloat16 *ovhi, *ovlo, *vphi, *vplo;
    cudaGetSymbolAddress((void**)&p_q,    g_q);
    cudaGetSymbolAddress((void**)&p_qln,  g_qln);
    cudaGetSymbolAddress((void**)&p_knw,  g_knw);
    cudaGetSymbolAddress((void**)&p_a,    g_a);
    cudaGetSymbolAddress((void**)&p_vidx, g_vidx);
    cudaGetSymbolAddress((void**)&p_w,    g_w);
    cudaGetSymbolAddress((void**)&xhi,    g_xhi);
    cudaGetSymbolAddress((void**)&xlo,    g_xlo);
    cudaGetSymbolAddress((void**)&wqhi,   g_wqhi);
    cudaGetSymbolAddress((void**)&wqlo,   g_wqlo);
    cudaGetSymbolAddress((void**)&qlnhi,  g_qlnhi);
    cudaGetSymbolAddress((void**)&qlnlo,  g_qlnlo);
    cudaGetSymbolAddress((void**)&knuhi,  g_knuhi);
    cudaGetSymbolAddress((void**)&knulo,  g_knulo);
    cudaGetSymbolAddress((void**)&ovhi,   g_ovhi);
    cudaGetSymbolAddress((void**)&ovlo,   g_ovlo);
    cudaGetSymbolAddress((void**)&vphi,   g_vphi);
    cudaGetSymbolAddress((void**)&vplo,   g_vplo);

    float* q0 = p_q;
    float* q1p = p_q + (size_t)BS_N * 512;
    float* q2p = p_q + (size_t)2 * BS_N * 512;
    float* q3p = p_q + (size_t)3 * BS_N * 512;
    float* a1 = p_a;
    float* a2 = p_a + (size_t)BS_N * HEAD * KEY_NUM;

    constexpr int STAGE64 = 2 * 64 * ROW_B + 2 * 128 * ROW_B;        // 24576
    constexpr int SMEM64  = 3 * STAGE64;                             // 73728
    cudaFuncSetAttribute(mma_gemm, cudaFuncAttributeMaxDynamicSharedMemorySize, SMEM64);

    // one-time side stream + events (infrastructure only; identical work every call)
    static cudaStream_t s1 = nullptr;
    static cudaEvent_t evFork = nullptr, evHead = nullptr, evMid = nullptr, evJoin = nullptr;
    if (s1 == nullptr) {
        cudaStreamCreateWithFlags(&s1, cudaStreamNonBlocking);
        cudaEventCreateWithFlags(&evFork, cudaEventDisableTiming);
        cudaEventCreateWithFlags(&evHead, cudaEventDisableTiming);
        cudaEventCreateWithFlags(&evMid,  cudaEventDisableTiming);
        cudaEventCreateWithFlags(&evJoin, cudaEventDisableTiming);
    }

    constexpr int HB = BS_N / 2;   // batch half

    // ---- fork side stream ----
    cudaEventRecord(evFork, 0);
    cudaStreamWaitEvent(s1, evFork, 0);

    // side stream: key LN + u/v contraction, vproj conversion (independent of q chain)
    keynorm_knu_kernel<<<(HEAD * 2 * KEY_NUM * 32) / 256, 256, 0, s1>>>(
        keys, u, v, p_knw, knuhi, knulo);
    conv_kernel<<<(HID * VDIM / 4) / 256, 256, 0, s1>>>(vproj_w, vphi, vplo, HID * VDIM / 4);
    cudaEventRecord(evHead, s1);

    // main stream: q chain
    conv_kernel<<<(BS_N * HID / 4) / 256, 256>>>(x, xhi, xlo, BS_N * HID / 4);
    conv_kernel<<<(2 * KDIM * HID / 4) / 256, 256>>>(q_proj_w, wqhi, wqlo, 2 * KDIM * HID / 4);

    // 1) q = x @ Wq^T  [4096 x 512], K=2048, split-K=4 -> partials q0..q3
    mma_gemm<<<dim3(512 / 128, BS_N / 64, 4), 256, SMEM64>>>(
        xhi, xlo, wqhi, wqlo, q0, HID, HID, 512, 512 / 32,
        512, 512, 0, (long long)BS_N * 512);

    // 2) per-half LayerNorm of q (fused split-K=4 reduction)
    qln_kernel<<<(BS_N * 2 * 32) / 256, 256>>>(q0, q1p, q2p, q3p, p_qln, qlnhi, qlnlo);

    // join side stream before a-GEMM (needs knu)
    cudaStreamWaitEvent(0, evHead, 0);

    // 3) approx scores a = qln_half @ knu_side^T  [4096 x 1024], K=256, z=side
    mma_gemm<<<dim3(1024 / 128, BS_N / 64, 2), 256, SMEM64>>>(
        qlnhi, qlnlo, knuhi, knulo, p_a, 512, KDIM, 1024, KDIM / 32,
        256, 0, 1024, (long long)BS_N * 1024);

    // ---- tail: pipeline batch halves across the two streams ----
    cudaEventRecord(evMid, 0);
    cudaStreamWaitEvent(s1, evMid, 0);

    // half 1 on side stream
    cand_kernel<<<(HB * HEAD * 32) / 256, 256, 0, s1>>>(
        a1, a2, p_qln, p_knw, core0, core1, shuffle, p_vidx, p_w, HB);
    gather_kernel<<<HB, 128, 0, s1>>>(values, p_vidx, p_w, ovhi, ovlo, HB);
    mma_gemm<<<dim3(2048 / 128, HB / 64, 1), 256, SMEM64, s1>>>(
        ovhi + (size_t)HB * VDIM, ovlo + (size_t)HB * VDIM, vphi, vplo,
        out + (size_t)HB * HID, VDIM, VDIM, 2048, VDIM / 32, 0, 0, 0, 0LL);
    cudaEventRecord(evJoin, s1);

    // half 0 on main stream
    cand_kernel<<<(HB * HEAD * 32) / 256, 256>>>(
        a1, a2, p_qln, p_knw, core0, core1, shuffle, p_vidx, p_w, 0);
    gather_kernel<<<HB, 128>>>(values, p_vidx, p_w, ovhi, ovlo, 0);
    mma_gemm<<<dim3(2048 / 128, HB / 64, 1), 256, SMEM64>>>(
        ovhi, ovlo, vphi, vplo, out, VDIM, VDIM, 2048, VDIM / 32, 0, 0, 0, 0LL);

    // join
    cudaStreamWaitEvent(0, evJoin, 0);
}